// round 7
// baseline (speedup 1.0000x reference)
#include <cuda_runtime.h>
#include <cuda_fp16.h>
#include <cstdint>

// ============================================================================
// PhaseCoherenceComputer: C[bh,q,k] = mean_h cos(phq - phk)
//   = (cos_q @ cos_k^T + sin_q @ sin_k^T) / 64
// 16 GEMMs [2048,128]@[128,2048]^T in fp16 (validated rel_err ~5.6e-5).
// 1/64 folded into A scratch. Scratch row (K=128): cos[0:64] sin[64:128].
// R5: multi-tile CTAs (4 N-tiles per CTA, resident A, double-buffered B with
// one-iteration-ahead cp.async prefetch), staged coalesced epilogue reusing
// the freed B buffer.
// ============================================================================

#define NBH 16
#define SEQ 2048
#define NH  64
#define KS  128
#define BM  128
#define BN  128
#define TILES 4          // N-tiles per CTA

// ---------------- scratch (device globals; no allocation APIs) --------------
__device__ __align__(16) __half gA[NBH * SEQ * KS];   // 8 MB (pre-scaled 1/64)
__device__ __align__(16) __half gB[NBH * SEQ * KS];   // 8 MB

__device__ __forceinline__ uint32_t smem_u32(const void* p) {
    uint32_t a;
    asm("{ .reg .u64 t; cvta.to.shared.u64 t, %1; cvt.u32.u64 %0, t; }"
        : "=r"(a) : "l"(p));
    return a;
}

#define CP_ASYNC_16(smem, gptr)                                                \
    asm volatile("cp.async.cg.shared.global [%0], [%1], 16;"                   \
                 :: "r"(smem), "l"(gptr))
#define CP_COMMIT()  asm volatile("cp.async.commit_group;" ::: "memory")
#define CP_WAIT(N)   asm volatile("cp.async.wait_group %0;" :: "n"(N) : "memory")

#define LDSM_X4(r0, r1, r2, r3, addr)                                          \
    asm volatile("ldmatrix.sync.aligned.m8n8.x4.shared.b16 {%0,%1,%2,%3}, [%4];" \
                 : "=r"(r0), "=r"(r1), "=r"(r2), "=r"(r3) : "r"(addr))

#define MMA_F16(c0, c1, c2, c3, a0, a1, a2, a3, b0, b1)                        \
    asm volatile("mma.sync.aligned.m16n8k16.row.col.f32.f16.f16.f32 "          \
                 "{%0,%1,%2,%3}, {%4,%5,%6,%7}, {%8,%9}, {%0,%1,%2,%3};"       \
                 : "+f"(c0), "+f"(c1), "+f"(c2), "+f"(c3)                      \
                 : "r"(a0), "r"(a1), "r"(a2), "r"(a3), "r"(b0), "r"(b1))

#define STG_CS_V4(gptr, x, y, z, w)                                            \
    asm volatile("st.global.cs.v4.f32 [%0], {%1,%2,%3,%4};"                    \
                 :: "l"(gptr), "f"(x), "f"(y), "f"(z), "f"(w) : "memory")

// ============================================================================
// Kernel 1: sincos -> fp16 scratch (A pre-scaled 1/NH). 4 harmonics/thread.
// ============================================================================
__global__ void phase_prep_kernel(const float* __restrict__ q,
                                  const float* __restrict__ k)
{
    const int NT = NBH * SEQ * (NH / 4);
    int idx = blockIdx.x * blockDim.x + threadIdx.x;
    if (idx >= 2 * NT) return;
    bool isQ = idx < NT;
    int li  = isQ ? idx : idx - NT;
    int row = li >> 4;
    int h4  = (li & 15) << 2;

    const float4 v = *(const float4*)((isQ ? q : k) + (size_t)row * NH + h4);
    const float sc = isQ ? (1.0f / (float)NH) : 1.0f;

    float s0, c0, s1, c1, s2, c2, s3, c3;
    sincosf(v.x, &s0, &c0);
    sincosf(v.y, &s1, &c1);
    sincosf(v.z, &s2, &c2);
    sincosf(v.w, &s3, &c3);

    __half2 ca = __floats2half2_rn(c0 * sc, c1 * sc);
    __half2 cb = __floats2half2_rn(c2 * sc, c3 * sc);
    __half2 sa = __floats2half2_rn(s0 * sc, s1 * sc);
    __half2 sb = __floats2half2_rn(s2 * sc, s3 * sc);

    __half* dst = (isQ ? gA : gB) + (size_t)row * KS;
    uint2 uc, us;
    uc.x = *reinterpret_cast<uint32_t*>(&ca);
    uc.y = *reinterpret_cast<uint32_t*>(&cb);
    us.x = *reinterpret_cast<uint32_t*>(&sa);
    us.y = *reinterpret_cast<uint32_t*>(&sb);
    *(uint2*)(dst + h4)      = uc;
    *(uint2*)(dst + 64 + h4) = us;
}

// ============================================================================
// Kernel 2: fp16 mma.sync GEMM. grid (4 ntGroups, 16 mt, 16 bh) = 1024 CTAs,
// 256 threads (2x4 warp grid, 64x32 warp tiles), 4 N-tiles per CTA.
// smem: A 32KB resident | B buf0 34KB | B buf1 34KB  (epi staging reuses the
// freed B buffer, 64 rows x 132-float stride per half).
// ============================================================================
#define A_BYTES  32768
#define B_BYTES  34816
#define EPI_STRIDE 132
#define SMEM_TOTAL (A_BYTES + 2 * B_BYTES)    // 102400

__global__ void __launch_bounds__(256, 2)
phase_gemm_kernel(float* __restrict__ out)
{
    extern __shared__ char smem[];
    const uint32_t sb = smem_u32(smem);
    const int tid  = threadIdx.x;
    const int wid  = tid >> 5;
    const int lane = tid & 31;
    const int wm   = wid >> 2;          // 0-1
    const int wn   = wid & 3;           // 0-3

    const int ntG = blockIdx.x;         // group of 4 N-tiles
    const int mt  = blockIdx.y;
    const int bh  = blockIdx.z;

    const __half* __restrict__ pA = gA + ((size_t)bh * SEQ + (size_t)mt * BM) * KS;
    const __half* __restrict__ pB0 =
        gB + ((size_t)bh * SEQ + (size_t)(ntG * TILES) * BN) * KS;  // +i*BN*KS per tile

    // gmem->smem tile copy mapping: row = r0 + t*16, chunk c (16B), 8 iters.
    // (t*16 is a multiple of 8, so the XOR swizzle term is t-invariant.)
    const int r0 = tid >> 4;
    const int c  = tid & 15;
    const uint32_t so0 = (uint32_t)(r0 * 256) +
                         ((uint32_t)((c & 8) | ((c & 7) ^ (r0 & 7))) << 4);
    const uint32_t go0 = (uint32_t)(r0 * KS + c * 8);   // elements

    // ---- prologue: A + B0 (group0), B1 (group1) ----
#pragma unroll
    for (int t = 0; t < 8; t++) {
        CP_ASYNC_16(sb + so0 + t * 4096,           pA  + go0 + t * 2048);
        CP_ASYNC_16(sb + A_BYTES + so0 + t * 4096, pB0 + go0 + t * 2048);
    }
    CP_COMMIT();
#pragma unroll
    for (int t = 0; t < 8; t++)
        CP_ASYNC_16(sb + A_BYTES + B_BYTES + so0 + t * 4096,
                    pB0 + (size_t)BN * KS + go0 + t * 2048);
    CP_COMMIT();

    // ldmatrix base rows
    const int rl = lane & 15;
    const int hc = lane >> 4;
    uint32_t aRow[4], bRow[2];
#pragma unroll
    for (int mf = 0; mf < 4; mf++) aRow[mf] = (uint32_t)(wm * 64 + mf * 16 + rl);
#pragma unroll
    for (int p = 0; p < 2; p++)   bRow[p]  = (uint32_t)(wn * 32 + p * 16 + rl);

    const int qg  = lane >> 2;
    const int cp2 = (lane & 3) * 2;

    float* const outMt = out + ((size_t)bh * SEQ + (size_t)mt * BM) * SEQ
                             + (size_t)(ntG * TILES) * BN;

#pragma unroll
    for (int i = 0; i < TILES; i++) {
        if (i < TILES - 1) { CP_WAIT(1); } else { CP_WAIT(0); }
        __syncthreads();

        float acc[4][4][4];
#pragma unroll
        for (int mf = 0; mf < 4; mf++)
#pragma unroll
            for (int nf = 0; nf < 4; nf++)
#pragma unroll
                for (int j = 0; j < 4; j++) acc[mf][nf][j] = 0.0f;

        const uint32_t bBase = sb + A_BYTES + (uint32_t)(i & 1) * B_BYTES;

        // ---- MMA: 8 k-slices of 16 ----
#pragma unroll
        for (int kk = 0; kk < 8; kk++) {
            const uint32_t chunk = (uint32_t)(kk * 2 + hc);
            uint32_t a[4][4];
#pragma unroll
            for (int mf = 0; mf < 4; mf++) {
                uint32_t r = aRow[mf];
                uint32_t sw = (chunk & 8) | ((chunk & 7) ^ (r & 7));
                LDSM_X4(a[mf][0], a[mf][1], a[mf][2], a[mf][3],
                        sb + r * 256 + (sw << 4));
            }
            uint32_t b[4][2];
#pragma unroll
            for (int p = 0; p < 2; p++) {
                uint32_t r = bRow[p];
                uint32_t sw = (chunk & 8) | ((chunk & 7) ^ (r & 7));
                uint32_t x0, x1, x2, x3;
                LDSM_X4(x0, x1, x2, x3, bBase + r * 256 + (sw << 4));
                b[p * 2][0]     = x0; b[p * 2][1]     = x2;
                b[p * 2 + 1][0] = x1; b[p * 2 + 1][1] = x3;
            }
#pragma unroll
            for (int mf = 0; mf < 4; mf++)
#pragma unroll
                for (int nf = 0; nf < 4; nf++)
                    MMA_F16(acc[mf][nf][0], acc[mf][nf][1],
                            acc[mf][nf][2], acc[mf][nf][3],
                            a[mf][0], a[mf][1], a[mf][2], a[mf][3],
                            b[nf][0], b[nf][1]);
        }
        __syncthreads();   // B(i) buffer now dead -> reuse as epi staging

        // ---- staged epilogue, two 64-row halves ----
        float* ep = (float*)(smem + A_BYTES + (size_t)(i & 1) * B_BYTES);
        float* obase = outMt + (size_t)i * BN;
#pragma unroll
        for (int h = 0; h < 2; h++) {
            if (wm == h) {
#pragma unroll
                for (int mf = 0; mf < 4; mf++) {
                    float* pr = ep + (size_t)(mf * 16 + qg) * EPI_STRIDE + cp2
                              + wn * 32;
#pragma unroll
                    for (int nf = 0; nf < 4; nf++) {
                        float* p0 = pr + nf * 8;
                        *(float2*)p0 =
                            make_float2(acc[mf][nf][0], acc[mf][nf][1]);
                        *(float2*)(p0 + 8 * EPI_STRIDE) =
                            make_float2(acc[mf][nf][2], acc[mf][nf][3]);
                    }
                }
            }
            __syncthreads();
#pragma unroll
            for (int t = 0; t < 8; t++) {
                int idx  = tid + t * 256;        // 0..2047 float4 of this half
                int lrow = idx >> 5;             // 0..63
                int f4   = idx & 31;
                const float4 v =
                    *(const float4*)(ep + (size_t)lrow * EPI_STRIDE + f4 * 4);
                STG_CS_V4(obase + (size_t)(h * 64 + lrow) * SEQ + f4 * 4,
                          v.x, v.y, v.z, v.w);
            }
            __syncthreads();
        }

        // ---- prefetch B(i+2) into the just-drained buffer ----
        if (i < TILES - 2) {
            const __half* pBn = pB0 + (size_t)(i + 2) * BN * KS;
#pragma unroll
            for (int t = 0; t < 8; t++)
                CP_ASYNC_16(sb + A_BYTES + (uint32_t)(i & 1) * B_BYTES
                                + so0 + t * 4096,
                            pBn + go0 + t * 2048);
            CP_COMMIT();
        }
    }
}

// ============================================================================
// launch
// ============================================================================
extern "C" void kernel_launch(void* const* d_in, const int* in_sizes, int n_in,
                              void* d_out, int out_size)
{
    const float* q = (const float*)d_in[0];
    const float* k = (const float*)d_in[1];
    float* out = (float*)d_out;

    cudaFuncSetAttribute(phase_gemm_kernel,
                         cudaFuncAttributeMaxDynamicSharedMemorySize, SMEM_TOTAL);

    const int NT = NBH * SEQ * (NH / 4);
    int threads = 256;
    int blocks = (2 * NT + threads - 1) / threads;
    phase_prep_kernel<<<blocks, threads>>>(q, k);

    dim3 grid(SEQ / BN / TILES, SEQ / BM, NBH);   // (4,16,16)
    phase_gemm_kernel<<<grid, 256, SMEM_TOTAL>>>(out);
}

// round 8
// speedup vs baseline: 1.2566x; 1.2566x over previous
#include <cuda_runtime.h>
#include <cuda_fp16.h>
#include <cstdint>

// ============================================================================
// PhaseCoherenceComputer: C[bh,q,k] = mean_h cos(phq - phk)
//   = (cos_q @ cos_k^T + sin_q @ sin_k^T) / 64
// 16 GEMMs [2048,128]@[128,2048]^T in fp16 (validated rel_err ~5.6e-5).
// 1/64 folded into A scratch. Scratch row (K=128 fp16): cos[0:64] sin[64:128].
// R8 = R3 (best, 72.4us) + single wait/barrier for both K stages +
//      st.global.cs direct epilogue + __sincosf prep.
// Staged smem epilogues regressed twice (R4/R5) -> direct scatter retained.
// ============================================================================

#define NBH 16
#define SEQ 2048
#define NH  64
#define KS  128          // scratch K width (cos 64 | sin 64)
#define BM  128
#define BN  128
#define BK  64
#define KITERS 2

// ---------------- scratch (device globals; no allocation APIs) --------------
__device__ __align__(16) __half gA[NBH * SEQ * KS];   // 8 MB (pre-scaled 1/64)
__device__ __align__(16) __half gB[NBH * SEQ * KS];   // 8 MB

__device__ __forceinline__ uint32_t smem_u32(const void* p) {
    uint32_t a;
    asm("{ .reg .u64 t; cvta.to.shared.u64 t, %1; cvt.u32.u64 %0, t; }"
        : "=r"(a) : "l"(p));
    return a;
}

#define CP_ASYNC_16(smem, gptr)                                                \
    asm volatile("cp.async.cg.shared.global [%0], [%1], 16;"                   \
                 :: "r"(smem), "l"(gptr))
#define CP_COMMIT()  asm volatile("cp.async.commit_group;" ::: "memory")
#define CP_WAIT(N)   asm volatile("cp.async.wait_group %0;" :: "n"(N) : "memory")

#define LDSM_X4(r0, r1, r2, r3, addr)                                          \
    asm volatile("ldmatrix.sync.aligned.m8n8.x4.shared.b16 {%0,%1,%2,%3}, [%4];" \
                 : "=r"(r0), "=r"(r1), "=r"(r2), "=r"(r3) : "r"(addr))

#define MMA_F16(c0, c1, c2, c3, a0, a1, a2, a3, b0, b1)                        \
    asm volatile("mma.sync.aligned.m16n8k16.row.col.f32.f16.f16.f32 "          \
                 "{%0,%1,%2,%3}, {%4,%5,%6,%7}, {%8,%9}, {%0,%1,%2,%3};"       \
                 : "+f"(c0), "+f"(c1), "+f"(c2), "+f"(c3)                      \
                 : "r"(a0), "r"(a1), "r"(a2), "r"(a3), "r"(b0), "r"(b1))

#define STG_CS_V2(gptr, x, y)                                                  \
    asm volatile("st.global.cs.v2.f32 [%0], {%1,%2};"                          \
                 :: "l"(gptr), "f"(x), "f"(y) : "memory")

// ============================================================================
// Kernel 1: __sincosf -> fp16 scratch (A pre-scaled 1/NH). 4 harmonics/thread.
// ============================================================================
__global__ void phase_prep_kernel(const float* __restrict__ q,
                                  const float* __restrict__ k)
{
    const int NT = NBH * SEQ * (NH / 4);    // 524288 threads per tensor
    int idx = blockIdx.x * blockDim.x + threadIdx.x;
    if (idx >= 2 * NT) return;
    bool isQ = idx < NT;
    int li  = isQ ? idx : idx - NT;
    int row = li >> 4;
    int h4  = (li & 15) << 2;

    const float4 v = *(const float4*)((isQ ? q : k) + (size_t)row * NH + h4);
    const float sc = isQ ? (1.0f / (float)NH) : 1.0f;

    float s0, c0, s1, c1, s2, c2, s3, c3;
    __sincosf(v.x, &s0, &c0);
    __sincosf(v.y, &s1, &c1);
    __sincosf(v.z, &s2, &c2);
    __sincosf(v.w, &s3, &c3);

    __half2 ca = __floats2half2_rn(c0 * sc, c1 * sc);
    __half2 cb = __floats2half2_rn(c2 * sc, c3 * sc);
    __half2 sa = __floats2half2_rn(s0 * sc, s1 * sc);
    __half2 sb = __floats2half2_rn(s2 * sc, s3 * sc);

    __half* dst = (isQ ? gA : gB) + (size_t)row * KS;
    uint2 uc, us;
    uc.x = *reinterpret_cast<uint32_t*>(&ca);
    uc.y = *reinterpret_cast<uint32_t*>(&cb);
    us.x = *reinterpret_cast<uint32_t*>(&sa);
    us.y = *reinterpret_cast<uint32_t*>(&sb);
    *(uint2*)(dst + h4)      = uc;
    *(uint2*)(dst + 64 + h4) = us;
}

// ============================================================================
// Kernel 2: fp16 mma.sync GEMM, BM=BN=128, BK=64 x2 stages issued up-front,
// ONE wait+barrier, barrier-free mainloop + direct .cs scatter epilogue.
// grid = (16,16,16), 256 threads (2x4 warps, 64x32 tiles).
// ============================================================================
#define STG_BYTES (2 * BM * BK * 2)           // 32768 (A tile + B tile)
#define SMEM_TOTAL (KITERS * STG_BYTES)       // 65536

__global__ void __launch_bounds__(256, 2)
phase_gemm_kernel(float* __restrict__ out)
{
    extern __shared__ char smem[];
    const uint32_t sb = smem_u32(smem);
    const int tid  = threadIdx.x;
    const int wid  = tid >> 5;
    const int lane = tid & 31;
    const int wm   = wid >> 2;          // 0-1
    const int wn   = wid & 3;           // 0-3

    const int nt = blockIdx.x;
    const int mt = blockIdx.y;
    const int bh = blockIdx.z;

    const __half* __restrict__ pA = gA + ((size_t)bh * SEQ + (size_t)mt * BM) * KS;
    const __half* __restrict__ pB = gB + ((size_t)bh * SEQ + (size_t)nt * BN) * KS;

    const int ldRow = tid >> 3;          // base row, +32 stride x4
    const int ldChk = tid & 7;           // 16B chunk in 128B smem row

    uint32_t stSm[4];
    size_t   stGm[4];
#pragma unroll
    for (int t = 0; t < 4; t++) {
        int row = ldRow + t * 32;
        stSm[t] = (uint32_t)(row * 128 + ((ldChk ^ (row & 7)) << 4));
        stGm[t] = (size_t)row * KS + ldChk * 8;
    }

    // ---- issue both K stages up front, single commit ----
#pragma unroll
    for (int s = 0; s < KITERS; s++) {
        uint32_t base = sb + s * STG_BYTES;
        const int off = s * BK;
#pragma unroll
        for (int t = 0; t < 4; t++) {
            CP_ASYNC_16(base + stSm[t],                 pA + stGm[t] + off);
            CP_ASYNC_16(base + (BM * BK * 2) + stSm[t], pB + stGm[t] + off);
        }
    }
    CP_COMMIT();

    // ldmatrix base rows
    const int rl = lane & 15;
    const int hc = lane >> 4;
    uint32_t aRow[4], bRow[2];
#pragma unroll
    for (int mf = 0; mf < 4; mf++) aRow[mf] = (uint32_t)(wm * 64 + mf * 16 + rl);
#pragma unroll
    for (int p = 0; p < 2; p++)   bRow[p]  = (uint32_t)(wn * 32 + p * 16 + rl);

    float acc[4][4][4];
#pragma unroll
    for (int mf = 0; mf < 4; mf++)
#pragma unroll
        for (int nf = 0; nf < 4; nf++)
#pragma unroll
            for (int j = 0; j < 4; j++) acc[mf][nf][j] = 0.0f;

    // ---- single wait + barrier, then barrier-free 8-slice mainloop ----
    CP_WAIT(0);
    __syncthreads();

#pragma unroll
    for (int ki = 0; ki < KITERS; ki++) {
        const uint32_t aBase = sb + ki * STG_BYTES;
        const uint32_t bBase = aBase + BM * BK * 2;
#pragma unroll
        for (int kk = 0; kk < 4; kk++) {
            const int kk2 = kk * 2;
            uint32_t a[4][4];
#pragma unroll
            for (int mf = 0; mf < 4; mf++) {
                uint32_t r = aRow[mf];
                uint32_t addr = aBase + r * 128 + ((((uint32_t)(kk2 + hc)) ^ (r & 7)) << 4);
                LDSM_X4(a[mf][0], a[mf][1], a[mf][2], a[mf][3], addr);
            }
            uint32_t b[4][2];
#pragma unroll
            for (int p = 0; p < 2; p++) {
                uint32_t r = bRow[p];
                uint32_t addr = bBase + r * 128 + ((((uint32_t)(kk2 + hc)) ^ (r & 7)) << 4);
                uint32_t x0, x1, x2, x3;
                LDSM_X4(x0, x1, x2, x3, addr);
                b[p * 2][0]     = x0; b[p * 2][1]     = x2;
                b[p * 2 + 1][0] = x1; b[p * 2 + 1][1] = x3;
            }
#pragma unroll
            for (int mf = 0; mf < 4; mf++)
#pragma unroll
                for (int nf = 0; nf < 4; nf++)
                    MMA_F16(acc[mf][nf][0], acc[mf][nf][1],
                            acc[mf][nf][2], acc[mf][nf][3],
                            a[mf][0], a[mf][1], a[mf][2], a[mf][3],
                            b[nf][0], b[nf][1]);
        }
    }

    // ---- epilogue: direct .cs scatter (scale pre-folded into A) ----
    const int qg  = lane >> 2;
    const int cp2 = (lane & 3) * 2;
    float* obase = out + ((size_t)bh * SEQ + (size_t)mt * BM + wm * 64) * SEQ
                       + (size_t)nt * BN + wn * 32;
#pragma unroll
    for (int mf = 0; mf < 4; mf++) {
#pragma unroll
        for (int nf = 0; nf < 4; nf++) {
            float* p0 = obase + (size_t)(mf * 16 + qg) * SEQ + nf * 8 + cp2;
            STG_CS_V2(p0,           acc[mf][nf][0], acc[mf][nf][1]);
            STG_CS_V2(p0 + 8 * SEQ, acc[mf][nf][2], acc[mf][nf][3]);
        }
    }
}

// ============================================================================
// launch
// ============================================================================
extern "C" void kernel_launch(void* const* d_in, const int* in_sizes, int n_in,
                              void* d_out, int out_size)
{
    const float* q = (const float*)d_in[0];
    const float* k = (const float*)d_in[1];
    float* out = (float*)d_out;

    cudaFuncSetAttribute(phase_gemm_kernel,
                         cudaFuncAttributeMaxDynamicSharedMemorySize, SMEM_TOTAL);

    const int NT = NBH * SEQ * (NH / 4);
    int threads = 256;
    int blocks = (2 * NT + threads - 1) / threads;
    phase_prep_kernel<<<blocks, threads>>>(q, k);

    dim3 grid(SEQ / BN, SEQ / BM, NBH);   // (16,16,16)
    phase_gemm_kernel<<<grid, 256, SMEM_TOTAL>>>(out);
}